// round 10
// baseline (speedup 1.0000x reference)
#include <cuda_runtime.h>
#include <cuda_fp16.h>
#include <math.h>

#define BSZ 32
#define SEQ 1024
#define EMB 768
#define HD  64

typedef unsigned long long ull;
typedef unsigned int uint32;

__device__ __forceinline__ ull pk2(float lo, float hi) {
    ull r; asm("mov.b64 %0, {%1, %2};" : "=l"(r) : "f"(lo), "f"(hi)); return r;
}
// pack two fp32 -> f16x2 (lo in low half)
__device__ __forceinline__ uint32 ph2(float lo, float hi) {
    uint32 r; asm("cvt.rn.f16x2.f32 %0, %1, %2;" : "=r"(r) : "f"(hi), "f"(lo)); return r;
}
__device__ __forceinline__ void mma_f16(float c[4],
    uint32 a0, uint32 a1, uint32 a2, uint32 a3, uint32 b0, uint32 b1)
{
    asm volatile(
        "mma.sync.aligned.m16n8k16.row.col.f32.f16.f16.f32 "
        "{%0,%1,%2,%3}, {%4,%5,%6,%7}, {%8,%9}, {%0,%1,%2,%3};"
        : "+f"(c[0]), "+f"(c[1]), "+f"(c[2]), "+f"(c[3])
        : "r"(a0), "r"(a1), "r"(a2), "r"(a3), "r"(b0), "r"(b1));
}

__device__ float g_q[BSZ * SEQ * HD];
__device__ float g_k[BSZ * SEQ * HD];
__device__ float g_v[BSZ * SEQ * HD];
__device__ float g_cos[SEQ * 32];
__device__ float g_sin[SEQ * 32];

// ---------------------------------------------------------------------------
// Kernel 0: RoPE cos/sin table
// ---------------------------------------------------------------------------
__global__ void rope_table_kernel()
{
    const int t = blockIdx.x * blockDim.x + threadIdx.x;
    if (t >= SEQ * 32) return;
    const int pos = t >> 5;
    const int pr  = t & 31;
    const float theta = expf((float)pr * -0.5756462732485114f);
    float sn, cs;
    sincosf((float)pos * theta, &sn, &cs);
    g_cos[t] = cs;
    g_sin[t] = sn;
}

// ---------------------------------------------------------------------------
// Kernel 1: QKV projection via fp16 m16n8k16 mma + RoPE epilogue (R8, passing).
// ---------------------------------------------------------------------------
#define XW 20   // words per smem row

__global__ __launch_bounds__(256) void qkv_rope_kernel(
    const float* __restrict__ x,
    const float* __restrict__ Wq,
    const float* __restrict__ Wk,
    const float* __restrict__ Wv)
{
    const int which = blockIdx.x;
    const float* __restrict__ W = (which == 0) ? Wq : ((which == 1) ? Wk : Wv);
    float* __restrict__ outp    = (which == 0) ? g_q : ((which == 1) ? g_k : g_v);

    const int m0 = blockIdx.y * 128;

    __shared__ uint32 xs[2][128 * XW];
    __shared__ uint32 ws[2][64 * XW];

    const int tid    = threadIdx.x;
    const int lane   = tid & 31;
    const int wid    = tid >> 5;
    const int warp_m = wid & 3;
    const int warp_n = wid >> 2;
    const int lr = lane >> 2;
    const int lc = lane & 3;

    const int xrow = tid >> 3;
    const int xkq  = tid & 7;

    uint2 rx[4], rw[2];

    float c[2][4][4];
    #pragma unroll
    for (int mt = 0; mt < 2; mt++)
        #pragma unroll
        for (int nt = 0; nt < 4; nt++)
            #pragma unroll
            for (int r = 0; r < 4; r++) c[mt][nt][r] = 0.f;

    #pragma unroll
    for (int q = 0; q < 4; q++) {
        float4 t = *(const float4*)&x[(size_t)(m0 + xrow + q * 32) * EMB + xkq * 4];
        rx[q] = make_uint2(ph2(t.x, t.y), ph2(t.z, t.w));
    }
    #pragma unroll
    for (int q = 0; q < 2; q++) {
        float4 t = *(const float4*)&W[(size_t)(xrow + q * 32) * EMB + xkq * 4];
        rw[q] = make_uint2(ph2(t.x, t.y), ph2(t.z, t.w));
    }
    #pragma unroll
    for (int q = 0; q < 4; q++)
        *(uint2*)&xs[0][(xrow + q * 32) * XW + xkq * 2] = rx[q];
    #pragma unroll
    for (int q = 0; q < 2; q++)
        *(uint2*)&ws[0][(xrow + q * 32) * XW + xkq * 2] = rw[q];
    __syncthreads();

    const int NCH = EMB / 32;   // 24
    for (int ec = 0; ec < NCH; ec++) {
        const int cur = ec & 1;
        const bool more = (ec + 1 < NCH);
        if (more) {
            const int e1 = (ec + 1) * 32;
            #pragma unroll
            for (int q = 0; q < 4; q++) {
                float4 t = *(const float4*)&x[(size_t)(m0 + xrow + q * 32) * EMB + e1 + xkq * 4];
                rx[q] = make_uint2(ph2(t.x, t.y), ph2(t.z, t.w));
            }
            #pragma unroll
            for (int q = 0; q < 2; q++) {
                float4 t = *(const float4*)&W[(size_t)(xrow + q * 32) * EMB + e1 + xkq * 4];
                rw[q] = make_uint2(ph2(t.x, t.y), ph2(t.z, t.w));
            }
        }

        #pragma unroll
        for (int ks = 0; ks < 2; ks++) {
            const int kb = ks * 8;
            uint32 a[2][4];
            #pragma unroll
            for (int mt = 0; mt < 2; mt++) {
                const int rb = warp_m * 32 + mt * 16 + lr;
                a[mt][0] = xs[cur][rb * XW + kb + lc];
                a[mt][1] = xs[cur][(rb + 8) * XW + kb + lc];
                a[mt][2] = xs[cur][rb * XW + kb + lc + 4];
                a[mt][3] = xs[cur][(rb + 8) * XW + kb + lc + 4];
            }
            uint32 bb[4][2];
            #pragma unroll
            for (int nt = 0; nt < 4; nt++) {
                const int nb = warp_n * 32 + nt * 8 + lr;
                bb[nt][0] = ws[cur][nb * XW + kb + lc];
                bb[nt][1] = ws[cur][nb * XW + kb + lc + 4];
            }
            #pragma unroll
            for (int mt = 0; mt < 2; mt++)
                #pragma unroll
                for (int nt = 0; nt < 4; nt++)
                    mma_f16(c[mt][nt], a[mt][0], a[mt][1], a[mt][2], a[mt][3],
                            bb[nt][0], bb[nt][1]);
        }

        if (more) {
            const int nxt = cur ^ 1;
            #pragma unroll
            for (int q = 0; q < 4; q++)
                *(uint2*)&xs[nxt][(xrow + q * 32) * XW + xkq * 2] = rx[q];
            #pragma unroll
            for (int q = 0; q < 2; q++)
                *(uint2*)&ws[nxt][(xrow + q * 32) * XW + xkq * 2] = rw[q];
            __syncthreads();
        }
    }

    if (which < 2) {
        #pragma unroll
        for (int mt = 0; mt < 2; mt++) {
            const int r0 = m0 + warp_m * 32 + mt * 16 + lr;
            const int r1 = r0 + 8;
            const int p0 = r0 & (SEQ - 1);
            const int p1 = r1 & (SEQ - 1);
            #pragma unroll
            for (int nt = 0; nt < 4; nt++) {
                const int d0   = warp_n * 32 + nt * 8 + 2 * lc;
                const int pair = d0 >> 1;
                {
                    const float cs = g_cos[p0 * 32 + pair];
                    const float sn = g_sin[p0 * 32 + pair];
                    const float av = c[mt][nt][0], bv = c[mt][nt][1];
                    *(ull*)&outp[(size_t)r0 * HD + d0] = pk2(av * cs - bv * sn, bv * cs + av * sn);
                }
                {
                    const float cs = g_cos[p1 * 32 + pair];
                    const float sn = g_sin[p1 * 32 + pair];
                    const float av = c[mt][nt][2], bv = c[mt][nt][3];
                    *(ull*)&outp[(size_t)r1 * HD + d0] = pk2(av * cs - bv * sn, bv * cs + av * sn);
                }
            }
        }
    } else {
        #pragma unroll
        for (int mt = 0; mt < 2; mt++) {
            const int r0 = m0 + warp_m * 32 + mt * 16 + lr;
            #pragma unroll
            for (int nt = 0; nt < 4; nt++) {
                const int d0 = warp_n * 32 + nt * 8 + 2 * lc;
                *(ull*)&outp[(size_t)r0 * HD + d0]       = pk2(c[mt][nt][0], c[mt][nt][1]);
                *(ull*)&outp[(size_t)(r0 + 8) * HD + d0] = pk2(c[mt][nt][2], c[mt][nt][3]);
            }
        }
    }
}

// ---------------------------------------------------------------------------
// Kernel 2: causal flash attention — fp16 m16n8k16, 128-row q tiles, 8 warps.
//   grid (8, 32), 256 threads. KV tiles of 64 double-buffered; Q in registers.
// ---------------------------------------------------------------------------
#define AW 36

__global__ __launch_bounds__(256) void attn_kernel(float* __restrict__ out)
{
    extern __shared__ uint32 smu[];
    uint32* Ps = smu;                     // [128 q][36w]    P fp16 [q][kv]
    uint32* Ks = Ps + 128 * AW;           // [2][64 kv][36w] K fp16 [kv][h]
    uint32* Vp = Ks + 2 * 64 * AW;        // [2][64 h][36w]  V paired [h][kvpair]

    const int b  = blockIdx.y;
    const int qt = (SEQ / 128 - 1) - blockIdx.x;   // largest work first
    const int q0 = qt * 128;

    const float* __restrict__ qp = g_q + ((size_t)b * SEQ + q0) * HD;
    const float* __restrict__ kp = g_k + (size_t)b * SEQ * HD;
    const float* __restrict__ vp = g_v + (size_t)b * SEQ * HD;

    const int tid  = threadIdx.x;
    const int lane = tid & 31;
    const int w    = tid >> 5;      // 0..7, warp rows w*16..+16
    const int lr   = lane >> 2;
    const int lc   = lane & 3;

    uint2  rk[4];
    uint32 rv[2][4];

    // ---- Q fragments -> registers ----
    uint32 qa[4][4];
    {
        const float* q0p = qp + (size_t)(w * 16 + lr) * HD;
        const float* q1p = q0p + 8 * HD;
        #pragma unroll
        for (int ks = 0; ks < 4; ks++) {
            const int k = ks * 16 + 2 * lc;
            float2 t0 = *(const float2*)&q0p[k];
            float2 t1 = *(const float2*)&q1p[k];
            float2 t2 = *(const float2*)&q0p[k + 8];
            float2 t3 = *(const float2*)&q1p[k + 8];
            qa[ks][0] = ph2(t0.x, t0.y);
            qa[ks][1] = ph2(t1.x, t1.y);
            qa[ks][2] = ph2(t2.x, t2.y);
            qa[ks][3] = ph2(t3.x, t3.y);
        }
    }

    // ---- prologue: K/V tile 0 ----
    #pragma unroll
    for (int q = 0; q < 4; q++) {
        const int p = tid + q * 256;
        float4 t = ((const float4*)(kp))[p];
        rk[q] = make_uint2(ph2(t.x, t.y), ph2(t.z, t.w));
    }
    #pragma unroll
    for (int q = 0; q < 2; q++) {
        const int p  = tid + q * 256;
        const int rp = p & 31, hq = p >> 5;
        float4 va = ((const float4*)(vp + (size_t)(2 * rp) * HD))[hq];
        float4 vb = ((const float4*)(vp + (size_t)(2 * rp + 1) * HD))[hq];
        rv[q][0] = ph2(va.x, vb.x); rv[q][1] = ph2(va.y, vb.y);
        rv[q][2] = ph2(va.z, vb.z); rv[q][3] = ph2(va.w, vb.w);
    }
    #pragma unroll
    for (int q = 0; q < 4; q++) {
        const int p = tid + q * 256;
        const int r = p >> 4, hq = p & 15;
        *(uint2*)&Ks[r * AW + hq * 2] = rk[q];
    }
    #pragma unroll
    for (int q = 0; q < 2; q++) {
        const int p  = tid + q * 256;
        const int rp = p & 31, hq = p >> 5;
        #pragma unroll
        for (int i = 0; i < 4; i++)
            Vp[(hq * 4 + i) * AW + rp] = rv[q][i];
    }
    __syncthreads();

    float m_r[2] = {-1e30f, -1e30f};
    float l_r[2] = {0.f, 0.f};
    float o[8][4];
    #pragma unroll
    for (int nt = 0; nt < 8; nt++)
        #pragma unroll
        for (int r = 0; r < 4; r++) o[nt][r] = 0.f;

    const float sc2 = 0.03608439182435161f * 1.4426950408889634f;  // scale*log2e
    const int ntiles = 2 * qt + 2;           // kv tiles covering rows q0..q0+127
    const int row0 = q0 + w * 16 + lr;
    const int row1 = row0 + 8;

    for (int t = 0; t < ntiles; t++) {
        const int cur  = t & 1;
        const bool more = (t + 1 < ntiles);
        uint32* Kc = Ks + cur * 64 * AW;
        uint32* Vc = Vp + cur * 64 * AW;

        if (more) {
            const int k1 = (t + 1) * 64;
            #pragma unroll
            for (int q = 0; q < 4; q++) {
                const int p = tid + q * 256;
                float4 tk = ((const float4*)(kp + (size_t)k1 * HD))[p];
                rk[q] = make_uint2(ph2(tk.x, tk.y), ph2(tk.z, tk.w));
            }
            #pragma unroll
            for (int q = 0; q < 2; q++) {
                const int p  = tid + q * 256;
                const int rp = p & 31, hq = p >> 5;
                float4 va = ((const float4*)(vp + (size_t)(k1 + 2 * rp) * HD))[hq];
                float4 vb = ((const float4*)(vp + (size_t)(k1 + 2 * rp + 1) * HD))[hq];
                rv[q][0] = ph2(va.x, vb.x); rv[q][1] = ph2(va.y, vb.y);
                rv[q][2] = ph2(va.z, vb.z); rv[q][3] = ph2(va.w, vb.w);
            }
        }

        // ---- S = Q K^T ----
        float s[8][4];
        #pragma unroll
        for (int nt = 0; nt < 8; nt++)
            #pragma unroll
            for (int r = 0; r < 4; r++) s[nt][r] = 0.f;

        #pragma unroll
        for (int ks = 0; ks < 4; ks++) {
            const int kb = ks * 8;
            #pragma unroll
            for (int nt = 0; nt < 8; nt++) {
                const int nb = nt * 8 + lr;
                const uint32 b0 = Kc[nb * AW + kb + lc];
                const uint32 b1 = Kc[nb * AW + kb + lc + 4];
                mma_f16(s[nt], qa[ks][0], qa[ks][1], qa[ks][2], qa[ks][3], b0, b1);
            }
        }

        // scale (log2 domain) + causal mask (only tiles overlapping the diagonal)
        const bool maybe_mask = (t * 64 + 63 > row0);
        #pragma unroll
        for (int nt = 0; nt < 8; nt++) {
            const int col = t * 64 + nt * 8 + 2 * lc;
            #pragma unroll
            for (int r = 0; r < 4; r++) {
                float sv = s[nt][r] * sc2;
                if (maybe_mask) {
                    const int gr = (r < 2) ? row0 : row1;
                    const int gc = col + (r & 1);
                    if (gc > gr) sv = -1e30f;
                }
                s[nt][r] = sv;
            }
        }

        // ---- online softmax ----
        float alpha[2];
        #pragma unroll
        for (int h = 0; h < 2; h++) {
            float rm = -1e30f;
            #pragma unroll
            for (int nt = 0; nt < 8; nt++)
                rm = fmaxf(rm, fmaxf(s[nt][2 * h], s[nt][2 * h + 1]));
            rm = fmaxf(rm, __shfl_xor_sync(0xffffffffu, rm, 1));
            rm = fmaxf(rm, __shfl_xor_sync(0xffffffffu, rm, 2));
            const float mnew = fmaxf(m_r[h], rm);
            alpha[h] = exp2f(m_r[h] - mnew);
            m_r[h] = mnew;

            float rs = 0.f;
            #pragma unroll
            for (int nt = 0; nt < 8; nt++) {
                const float p0 = exp2f(s[nt][2 * h]     - mnew);
                const float p1 = exp2f(s[nt][2 * h + 1] - mnew);
                s[nt][2 * h] = p0; s[nt][2 * h + 1] = p1;
                rs += p0 + p1;
            }
            rs += __shfl_xor_sync(0xffffffffu, rs, 1);
            rs += __shfl_xor_sync(0xffffffffu, rs, 2);
            l_r[h] = l_r[h] * alpha[h] + rs;
        }

        // rescale O; stage P as fp16 (warp-private rows)
        const int prow = w * 16 + lr;
        #pragma unroll
        for (int nt = 0; nt < 8; nt++) {
            o[nt][0] *= alpha[0]; o[nt][1] *= alpha[0];
            o[nt][2] *= alpha[1]; o[nt][3] *= alpha[1];
            Ps[prow * AW + nt * 4 + lc]       = ph2(s[nt][0], s[nt][1]);
            Ps[(prow + 8) * AW + nt * 4 + lc] = ph2(s[nt][2], s[nt][3]);
        }
        __syncwarp();

        // ---- O += P V ----
        #pragma unroll
        for (int ks = 0; ks < 4; ks++) {
            const int kb = ks * 8;
            const uint32 a0 = Ps[prow * AW + kb + lc];
            const uint32 a1 = Ps[(prow + 8) * AW + kb + lc];
            const uint32 a2 = Ps[prow * AW + kb + lc + 4];
            const uint32 a3 = Ps[(prow + 8) * AW + kb + lc + 4];
            #pragma unroll
            for (int nt = 0; nt < 8; nt++) {
                const int nb = nt * 8 + lr;
                const uint32 b0 = Vc[nb * AW + kb + lc];
                const uint32 b1 = Vc[nb * AW + kb + lc + 4];
                mma_f16(o[nt], a0, a1, a2, a3, b0, b1);
            }
        }

        if (more) {
            const int nxt = cur ^ 1;
            uint32* Kn = Ks + nxt * 64 * AW;
            uint32* Vn = Vp + nxt * 64 * AW;
            #pragma unroll
            for (int q = 0; q < 4; q++) {
                const int p = tid + q * 256;
                const int r = p >> 4, hq = p & 15;
                *(uint2*)&Kn[r * AW + hq * 2] = rk[q];
            }
            #pragma unroll
            for (int q = 0; q < 2; q++) {
                const int p  = tid + q * 256;
                const int rp = p & 31, hq = p >> 5;
                #pragma unroll
                for (int i = 0; i < 4; i++)
                    Vn[(hq * 4 + i) * AW + rp] = rv[q][i];
            }
            __syncthreads();
        }
    }

    const float il0 = 1.0f / l_r[0];
    const float il1 = 1.0f / l_r[1];
    #pragma unroll
    for (int nt = 0; nt < 8; nt++) {
        const int d0 = nt * 8 + 2 * lc;
        *(ull*)&out[((size_t)b * SEQ + row0) * HD + d0] = pk2(o[nt][0] * il0, o[nt][1] * il0);
        *(ull*)&out[((size_t)b * SEQ + row1) * HD + d0] = pk2(o[nt][2] * il1, o[nt][3] * il1);
    }
}

extern "C" void kernel_launch(void* const* d_in, const int* in_sizes, int n_in,
                              void* d_out, int out_size)
{
    const float* x  = (const float*)d_in[0];
    const float* Wq = (const float*)d_in[1];
    const float* Wk = (const float*)d_in[2];
    const float* Wv = (const float*)d_in[3];
    float* out = (float*)d_out;

    rope_table_kernel<<<(SEQ * 32 + 255) / 256, 256>>>();

    dim3 g1(3, (BSZ * SEQ) / 128);
    qkv_rope_kernel<<<g1, 256>>>(x, Wq, Wk, Wv);

    const int smem = (128 * AW + 2 * 64 * AW + 2 * 64 * AW) * (int)sizeof(uint32); // 55296 B
    cudaFuncSetAttribute(attn_kernel, cudaFuncAttributeMaxDynamicSharedMemorySize, smem);
    dim3 g2(SEQ / 128, BSZ);
    attn_kernel<<<g2, 256, smem>>>(out);
}

// round 11
// speedup vs baseline: 1.0656x; 1.0656x over previous
#include <cuda_runtime.h>
#include <cuda_fp16.h>
#include <math.h>

#define BSZ 32
#define SEQ 1024
#define EMB 768
#define HD  64

typedef unsigned long long ull;
typedef unsigned int uint32;

__device__ __forceinline__ ull pk2(float lo, float hi) {
    ull r; asm("mov.b64 %0, {%1, %2};" : "=l"(r) : "f"(lo), "f"(hi)); return r;
}
// pack two fp32 -> f16x2 (lo in low half)
__device__ __forceinline__ uint32 ph2(float lo, float hi) {
    uint32 r; asm("cvt.rn.f16x2.f32 %0, %1, %2;" : "=r"(r) : "f"(hi), "f"(lo)); return r;
}
__device__ __forceinline__ void mma_f16(float c[4],
    uint32 a0, uint32 a1, uint32 a2, uint32 a3, uint32 b0, uint32 b1)
{
    asm volatile(
        "mma.sync.aligned.m16n8k16.row.col.f32.f16.f16.f32 "
        "{%0,%1,%2,%3}, {%4,%5,%6,%7}, {%8,%9}, {%0,%1,%2,%3};"
        : "+f"(c[0]), "+f"(c[1]), "+f"(c[2]), "+f"(c[3])
        : "r"(a0), "r"(a1), "r"(a2), "r"(a3), "r"(b0), "r"(b1));
}

__device__ float g_q[BSZ * SEQ * HD];
__device__ float g_k[BSZ * SEQ * HD];
__device__ float g_v[BSZ * SEQ * HD];
__device__ float g_cos[SEQ * 32];
__device__ float g_sin[SEQ * 32];

// ---------------------------------------------------------------------------
// Kernel 0: RoPE cos/sin table
// ---------------------------------------------------------------------------
__global__ void rope_table_kernel()
{
    const int t = blockIdx.x * blockDim.x + threadIdx.x;
    if (t >= SEQ * 32) return;
    const int pos = t >> 5;
    const int pr  = t & 31;
    const float theta = expf((float)pr * -0.5756462732485114f);
    float sn, cs;
    sincosf((float)pos * theta, &sn, &cs);
    g_cos[t] = cs;
    g_sin[t] = sn;
}

// ---------------------------------------------------------------------------
// Kernel 1: QKV projection via fp16 m16n8k16 mma + RoPE epilogue (R8, passing).
// ---------------------------------------------------------------------------
#define XW 20   // words per smem row

__global__ __launch_bounds__(256) void qkv_rope_kernel(
    const float* __restrict__ x,
    const float* __restrict__ Wq,
    const float* __restrict__ Wk,
    const float* __restrict__ Wv)
{
    const int which = blockIdx.x;
    const float* __restrict__ W = (which == 0) ? Wq : ((which == 1) ? Wk : Wv);
    float* __restrict__ outp    = (which == 0) ? g_q : ((which == 1) ? g_k : g_v);

    const int m0 = blockIdx.y * 128;

    __shared__ uint32 xs[2][128 * XW];
    __shared__ uint32 ws[2][64 * XW];

    const int tid    = threadIdx.x;
    const int lane   = tid & 31;
    const int wid    = tid >> 5;
    const int warp_m = wid & 3;
    const int warp_n = wid >> 2;
    const int lr = lane >> 2;
    const int lc = lane & 3;

    const int xrow = tid >> 3;
    const int xkq  = tid & 7;

    uint2 rx[4], rw[2];

    float c[2][4][4];
    #pragma unroll
    for (int mt = 0; mt < 2; mt++)
        #pragma unroll
        for (int nt = 0; nt < 4; nt++)
            #pragma unroll
            for (int r = 0; r < 4; r++) c[mt][nt][r] = 0.f;

    #pragma unroll
    for (int q = 0; q < 4; q++) {
        float4 t = *(const float4*)&x[(size_t)(m0 + xrow + q * 32) * EMB + xkq * 4];
        rx[q] = make_uint2(ph2(t.x, t.y), ph2(t.z, t.w));
    }
    #pragma unroll
    for (int q = 0; q < 2; q++) {
        float4 t = *(const float4*)&W[(size_t)(xrow + q * 32) * EMB + xkq * 4];
        rw[q] = make_uint2(ph2(t.x, t.y), ph2(t.z, t.w));
    }
    #pragma unroll
    for (int q = 0; q < 4; q++)
        *(uint2*)&xs[0][(xrow + q * 32) * XW + xkq * 2] = rx[q];
    #pragma unroll
    for (int q = 0; q < 2; q++)
        *(uint2*)&ws[0][(xrow + q * 32) * XW + xkq * 2] = rw[q];
    __syncthreads();

    const int NCH = EMB / 32;   // 24
    for (int ec = 0; ec < NCH; ec++) {
        const int cur = ec & 1;
        const bool more = (ec + 1 < NCH);
        if (more) {
            const int e1 = (ec + 1) * 32;
            #pragma unroll
            for (int q = 0; q < 4; q++) {
                float4 t = *(const float4*)&x[(size_t)(m0 + xrow + q * 32) * EMB + e1 + xkq * 4];
                rx[q] = make_uint2(ph2(t.x, t.y), ph2(t.z, t.w));
            }
            #pragma unroll
            for (int q = 0; q < 2; q++) {
                float4 t = *(const float4*)&W[(size_t)(xrow + q * 32) * EMB + e1 + xkq * 4];
                rw[q] = make_uint2(ph2(t.x, t.y), ph2(t.z, t.w));
            }
        }

        #pragma unroll
        for (int ks = 0; ks < 2; ks++) {
            const int kb = ks * 8;
            uint32 a[2][4];
            #pragma unroll
            for (int mt = 0; mt < 2; mt++) {
                const int rb = warp_m * 32 + mt * 16 + lr;
                a[mt][0] = xs[cur][rb * XW + kb + lc];
                a[mt][1] = xs[cur][(rb + 8) * XW + kb + lc];
                a[mt][2] = xs[cur][rb * XW + kb + lc + 4];
                a[mt][3] = xs[cur][(rb + 8) * XW + kb + lc + 4];
            }
            uint32 bb[4][2];
            #pragma unroll
            for (int nt = 0; nt < 4; nt++) {
                const int nb = warp_n * 32 + nt * 8 + lr;
                bb[nt][0] = ws[cur][nb * XW + kb + lc];
                bb[nt][1] = ws[cur][nb * XW + kb + lc + 4];
            }
            #pragma unroll
            for (int mt = 0; mt < 2; mt++)
                #pragma unroll
                for (int nt = 0; nt < 4; nt++)
                    mma_f16(c[mt][nt], a[mt][0], a[mt][1], a[mt][2], a[mt][3],
                            bb[nt][0], bb[nt][1]);
        }

        if (more) {
            const int nxt = cur ^ 1;
            #pragma unroll
            for (int q = 0; q < 4; q++)
                *(uint2*)&xs[nxt][(xrow + q * 32) * XW + xkq * 2] = rx[q];
            #pragma unroll
            for (int q = 0; q < 2; q++)
                *(uint2*)&ws[nxt][(xrow + q * 32) * XW + xkq * 2] = rw[q];
            __syncthreads();
        }
    }

    if (which < 2) {
        #pragma unroll
        for (int mt = 0; mt < 2; mt++) {
            const int r0 = m0 + warp_m * 32 + mt * 16 + lr;
            const int r1 = r0 + 8;
            const int p0 = r0 & (SEQ - 1);
            const int p1 = r1 & (SEQ - 1);
            #pragma unroll
            for (int nt = 0; nt < 4; nt++) {
                const int d0   = warp_n * 32 + nt * 8 + 2 * lc;
                const int pair = d0 >> 1;
                {
                    const float cs = g_cos[p0 * 32 + pair];
                    const float sn = g_sin[p0 * 32 + pair];
                    const float av = c[mt][nt][0], bv = c[mt][nt][1];
                    *(ull*)&outp[(size_t)r0 * HD + d0] = pk2(av * cs - bv * sn, bv * cs + av * sn);
                }
                {
                    const float cs = g_cos[p1 * 32 + pair];
                    const float sn = g_sin[p1 * 32 + pair];
                    const float av = c[mt][nt][2], bv = c[mt][nt][3];
                    *(ull*)&outp[(size_t)r1 * HD + d0] = pk2(av * cs - bv * sn, bv * cs + av * sn);
                }
            }
        }
    } else {
        #pragma unroll
        for (int mt = 0; mt < 2; mt++) {
            const int r0 = m0 + warp_m * 32 + mt * 16 + lr;
            #pragma unroll
            for (int nt = 0; nt < 4; nt++) {
                const int d0 = warp_n * 32 + nt * 8 + 2 * lc;
                *(ull*)&outp[(size_t)r0 * HD + d0]       = pk2(c[mt][nt][0], c[mt][nt][1]);
                *(ull*)&outp[(size_t)(r0 + 8) * HD + d0] = pk2(c[mt][nt][2], c[mt][nt][3]);
            }
        }
    }
}

// ---------------------------------------------------------------------------
// Kernel 2: causal flash attention — fp16 m16n8k16, register-resident P.
//   64-row q tiles, 128 threads, KV double-buffered. Q pre-scaled by sc*log2e.
// ---------------------------------------------------------------------------
#define AW 36

__global__ __launch_bounds__(128) void attn_kernel(float* __restrict__ out)
{
    extern __shared__ uint32 smu[];
    uint32* Ks = smu;                     // [2][64 kv][36w]  K fp16 [kv][h]
    uint32* Vp = Ks + 2 * 64 * AW;        // [2][64 h][36w]   V paired [h][kvpair]

    const int b  = blockIdx.y;
    const int qt = (SEQ / 64 - 1) - blockIdx.x;   // largest work first
    const int q0 = qt * 64;

    const float* __restrict__ qp = g_q + ((size_t)b * SEQ + q0) * HD;
    const float* __restrict__ kp = g_k + (size_t)b * SEQ * HD;
    const float* __restrict__ vp = g_v + (size_t)b * SEQ * HD;

    const int tid  = threadIdx.x;
    const int lane = tid & 31;
    const int w    = tid >> 5;
    const int lr   = lane >> 2;
    const int lc   = lane & 3;

    uint2  rk[8];
    uint32 rv[4][4];

    const float sc2 = 0.03608439182435161f * 1.4426950408889634f;  // scale*log2e

    // ---- Q fragments -> registers (pre-scaled by sc2) ----
    uint32 qa[4][4];
    {
        const float* q0p = qp + (size_t)(w * 16 + lr) * HD;
        const float* q1p = q0p + 8 * HD;
        #pragma unroll
        for (int ks = 0; ks < 4; ks++) {
            const int k = ks * 16 + 2 * lc;
            float2 t0 = *(const float2*)&q0p[k];
            float2 t1 = *(const float2*)&q1p[k];
            float2 t2 = *(const float2*)&q0p[k + 8];
            float2 t3 = *(const float2*)&q1p[k + 8];
            qa[ks][0] = ph2(t0.x * sc2, t0.y * sc2);
            qa[ks][1] = ph2(t1.x * sc2, t1.y * sc2);
            qa[ks][2] = ph2(t2.x * sc2, t2.y * sc2);
            qa[ks][3] = ph2(t3.x * sc2, t3.y * sc2);
        }
    }

    // ---- prologue: K/V tile 0 ----
    #pragma unroll
    for (int q = 0; q < 8; q++) {
        const int p = tid + q * 128;
        float4 t = ((const float4*)(kp))[p];
        rk[q] = make_uint2(ph2(t.x, t.y), ph2(t.z, t.w));
    }
    #pragma unroll
    for (int q = 0; q < 4; q++) {
        const int p  = tid + q * 128;
        const int rp = p & 31, hq = p >> 5;
        float4 va = ((const float4*)(vp + (size_t)(2 * rp) * HD))[hq];
        float4 vb = ((const float4*)(vp + (size_t)(2 * rp + 1) * HD))[hq];
        rv[q][0] = ph2(va.x, vb.x); rv[q][1] = ph2(va.y, vb.y);
        rv[q][2] = ph2(va.z, vb.z); rv[q][3] = ph2(va.w, vb.w);
    }
    #pragma unroll
    for (int q = 0; q < 8; q++) {
        const int p = tid + q * 128;
        const int r = p >> 4, hq = p & 15;
        *(uint2*)&Ks[r * AW + hq * 2] = rk[q];
    }
    #pragma unroll
    for (int q = 0; q < 4; q++) {
        const int p  = tid + q * 128;
        const int rp = p & 31, hq = p >> 5;
        #pragma unroll
        for (int i = 0; i < 4; i++)
            Vp[(hq * 4 + i) * AW + rp] = rv[q][i];
    }
    __syncthreads();

    float m_r[2] = {-1e30f, -1e30f};
    float l_r[2] = {0.f, 0.f};
    float o[8][4];
    #pragma unroll
    for (int nt = 0; nt < 8; nt++)
        #pragma unroll
        for (int r = 0; r < 4; r++) o[nt][r] = 0.f;

    const int ntiles = qt + 1;
    const int row0 = q0 + w * 16 + lr;
    const int row1 = row0 + 8;

    for (int t = 0; t < ntiles; t++) {
        const int cur  = t & 1;
        const bool more = (t + 1 < ntiles);
        uint32* Kc = Ks + cur * 64 * AW;
        uint32* Vc = Vp + cur * 64 * AW;

        if (more) {
            const int k1 = (t + 1) * 64;
            #pragma unroll
            for (int q = 0; q < 8; q++) {
                const int p = tid + q * 128;
                float4 tk = ((const float4*)(kp + (size_t)k1 * HD))[p];
                rk[q] = make_uint2(ph2(tk.x, tk.y), ph2(tk.z, tk.w));
            }
            #pragma unroll
            for (int q = 0; q < 4; q++) {
                const int p  = tid + q * 128;
                const int rp = p & 31, hq = p >> 5;
                float4 va = ((const float4*)(vp + (size_t)(k1 + 2 * rp) * HD))[hq];
                float4 vb = ((const float4*)(vp + (size_t)(k1 + 2 * rp + 1) * HD))[hq];
                rv[q][0] = ph2(va.x, vb.x); rv[q][1] = ph2(va.y, vb.y);
                rv[q][2] = ph2(va.z, vb.z); rv[q][3] = ph2(va.w, vb.w);
            }
        }

        // ---- S = (sc2*Q) K^T : already in log2 softmax domain ----
        float s[8][4];
        #pragma unroll
        for (int nt = 0; nt < 8; nt++)
            #pragma unroll
            for (int r = 0; r < 4; r++) s[nt][r] = 0.f;

        #pragma unroll
        for (int ks = 0; ks < 4; ks++) {
            const int kb = ks * 8;
            #pragma unroll
            for (int nt = 0; nt < 8; nt++) {
                const int nb = nt * 8 + lr;
                const uint32 b0 = Kc[nb * AW + kb + lc];
                const uint32 b1 = Kc[nb * AW + kb + lc + 4];
                mma_f16(s[nt], qa[ks][0], qa[ks][1], qa[ks][2], qa[ks][3], b0, b1);
            }
        }

        // causal mask (diagonal tile only)
        if (t == qt) {
            #pragma unroll
            for (int nt = 0; nt < 8; nt++) {
                const int col = q0 + nt * 8 + 2 * lc;
                #pragma unroll
                for (int r = 0; r < 4; r++) {
                    const int gr = (r < 2) ? row0 : row1;
                    const int gc = col + (r & 1);
                    if (gc > gr) s[nt][r] = -1e30f;
                }
            }
        }

        // ---- online softmax ----
        float alpha[2];
        #pragma unroll
        for (int h = 0; h < 2; h++) {
            float rm = -1e30f;
            #pragma unroll
            for (int nt = 0; nt < 8; nt++)
                rm = fmaxf(rm, fmaxf(s[nt][2 * h], s[nt][2 * h + 1]));
            rm = fmaxf(rm, __shfl_xor_sync(0xffffffffu, rm, 1));
            rm = fmaxf(rm, __shfl_xor_sync(0xffffffffu, rm, 2));
            const float mnew = fmaxf(m_r[h], rm);
            alpha[h] = exp2f(m_r[h] - mnew);
            m_r[h] = mnew;

            float rs = 0.f;
            #pragma unroll
            for (int nt = 0; nt < 8; nt++) {
                const float p0 = exp2f(s[nt][2 * h]     - mnew);
                const float p1 = exp2f(s[nt][2 * h + 1] - mnew);
                s[nt][2 * h] = p0; s[nt][2 * h + 1] = p1;
                rs += p0 + p1;
            }
            rs += __shfl_xor_sync(0xffffffffu, rs, 1);
            rs += __shfl_xor_sync(0xffffffffu, rs, 2);
            l_r[h] = l_r[h] * alpha[h] + rs;
        }

        // rescale O only if any row's max moved (uniform-ish branch)
        if (__any_sync(0xffffffffu, (alpha[0] < 1.0f) | (alpha[1] < 1.0f))) {
            #pragma unroll
            for (int nt = 0; nt < 8; nt++) {
                o[nt][0] *= alpha[0]; o[nt][1] *= alpha[0];
                o[nt][2] *= alpha[1]; o[nt][3] *= alpha[1];
            }
        }

        // ---- P fragments in registers (C-fragment == A-fragment layout) ----
        uint32 pA[8][2];
        #pragma unroll
        for (int nt = 0; nt < 8; nt++) {
            pA[nt][0] = ph2(s[nt][0], s[nt][1]);
            pA[nt][1] = ph2(s[nt][2], s[nt][3]);
        }

        // ---- O += P V ----
        #pragma unroll
        for (int ks = 0; ks < 4; ks++) {
            const int kb = ks * 8;
            const uint32 a0 = pA[2 * ks][0];
            const uint32 a1 = pA[2 * ks][1];
            const uint32 a2 = pA[2 * ks + 1][0];
            const uint32 a3 = pA[2 * ks + 1][1];
            #pragma unroll
            for (int nt = 0; nt < 8; nt++) {
                const int nb = nt * 8 + lr;
                const uint32 b0 = Vc[nb * AW + kb + lc];
                const uint32 b1 = Vc[nb * AW + kb + lc + 4];
                mma_f16(o[nt], a0, a1, a2, a3, b0, b1);
            }
        }

        if (more) {
            const int nxt = cur ^ 1;
            uint32* Kn = Ks + nxt * 64 * AW;
            uint32* Vn = Vp + nxt * 64 * AW;
            #pragma unroll
            for (int q = 0; q < 8; q++) {
                const int p = tid + q * 128;
                const int r = p >> 4, hq = p & 15;
                *(uint2*)&Kn[r * AW + hq * 2] = rk[q];
            }
            #pragma unroll
            for (int q = 0; q < 4; q++) {
                const int p  = tid + q * 128;
                const int rp = p & 31, hq = p >> 5;
                #pragma unroll
                for (int i = 0; i < 4; i++)
                    Vn[(hq * 4 + i) * AW + rp] = rv[q][i];
            }
            __syncthreads();
        }
    }

    const float il0 = 1.0f / l_r[0];
    const float il1 = 1.0f / l_r[1];
    #pragma unroll
    for (int nt = 0; nt < 8; nt++) {
        const int d0 = nt * 8 + 2 * lc;
        *(ull*)&out[((size_t)b * SEQ + row0) * HD + d0] = pk2(o[nt][0] * il0, o[nt][1] * il0);
        *(ull*)&out[((size_t)b * SEQ + row1) * HD + d0] = pk2(o[nt][2] * il1, o[nt][3] * il1);
    }
}

extern "C" void kernel_launch(void* const* d_in, const int* in_sizes, int n_in,
                              void* d_out, int out_size)
{
    const float* x  = (const float*)d_in[0];
    const float* Wq = (const float*)d_in[1];
    const float* Wk = (const float*)d_in[2];
    const float* Wv = (const float*)d_in[3];
    float* out = (float*)d_out;

    rope_table_kernel<<<(SEQ * 32 + 255) / 256, 256>>>();

    dim3 g1(3, (BSZ * SEQ) / 128);
    qkv_rope_kernel<<<g1, 256>>>(x, Wq, Wk, Wv);

    const int smem = (2 * 64 * AW + 2 * 64 * AW) * (int)sizeof(uint32); // 36864 B
    cudaFuncSetAttribute(attn_kernel, cudaFuncAttributeMaxDynamicSharedMemorySize, smem);
    dim3 g2(SEQ / 64, BSZ);
    attn_kernel<<<g2, 128, smem>>>(out);
}